// round 1
// baseline (speedup 1.0000x reference)
#include <cuda_runtime.h>
#include <cuda_bf16.h>

// Problem constants (fixed by the dataset): N=50000, E=800000, D=128.
#define D 128
#define MAXN 65536

__device__ int   g_deg[MAXN];
__device__ float g_dinv[MAXN];

// ---------------------------------------------------------------------------
// K1: deg[i] = 1 (self-loop)
// ---------------------------------------------------------------------------
__global__ void k_deg_init(int N) {
    int i = blockIdx.x * blockDim.x + threadIdx.x;
    if (i < N) g_deg[i] = 1;
}

// ---------------------------------------------------------------------------
// K2: deg[dst[e]] += 1
// ---------------------------------------------------------------------------
__global__ void k_deg_count(const int* __restrict__ adj, int E) {
    int e = blockIdx.x * blockDim.x + threadIdx.x;
    if (e < E) atomicAdd(&g_deg[adj[E + e]], 1);
}

// ---------------------------------------------------------------------------
// K3: dinv[i] = rsqrt(deg[i]);  out[i][:] = x[i][:] * dinv[i]^2  (self-loop msg)
// one thread per float4 (N*32 threads)
// ---------------------------------------------------------------------------
__global__ void k_init_agg(const float4* __restrict__ x4, float4* __restrict__ out4, int N) {
    int i = blockIdx.x * blockDim.x + threadIdx.x;
    if (i >= N * (D / 4)) return;
    int node = i >> 5;
    int j    = i & 31;
    float dv = rsqrtf((float)g_deg[node]);
    if (j == 0) g_dinv[node] = dv;
    float w = dv * dv;
    float4 v = x4[i];
    v.x *= w; v.y *= w; v.z *= w; v.w *= w;
    out4[i] = v;
}

// ---------------------------------------------------------------------------
// K4: scatter — one warp per edge.
//   out[dst] += x[src] * dinv[src] * dinv[dst]   via red.global.add.v4.f32
// ---------------------------------------------------------------------------
__global__ void k_scatter(const int* __restrict__ adj,
                          const float4* __restrict__ x4,
                          float4* __restrict__ out4, int E) {
    int gt   = blockIdx.x * blockDim.x + threadIdx.x;
    int e    = gt >> 5;
    int lane = gt & 31;
    if (e >= E) return;
    int s = __ldg(&adj[e]);
    int t = __ldg(&adj[E + e]);
    float w = g_dinv[s] * g_dinv[t];
    float4 v = x4[s * 32 + lane];
    v.x *= w; v.y *= w; v.z *= w; v.w *= w;
    float4* p = out4 + t * 32 + lane;
    asm volatile("red.global.add.v4.f32 [%0], {%1, %2, %3, %4};"
                 :: "l"(p), "f"(v.x), "f"(v.y), "f"(v.z), "f"(v.w)
                 : "memory");
}

// ---------------------------------------------------------------------------
// K5: fused GEMM (K=256: [aggx | x] @ [W_gcn ; W_lin]) + bias + eps + LayerNorm
//
// Block: 256 threads, 32 rows x 128 cols; thread = 4 rows x 4 cols.
// tx = tid&31 (col group, cols tx*4..tx*4+3), ty = tid>>5 (row group,
// rows ty*4..ty*4+3). Each warp is a single ty -> A-tile reads broadcast.
// K staged in 4 chunks of 64 (static smem 40KB: W 32KB + A 8KB).
// ---------------------------------------------------------------------------
#define BM 32
#define KC 64

__global__ void __launch_bounds__(256)
k_gemm_ln(const float* __restrict__ x,
          const float* __restrict__ Wg,
          const float* __restrict__ Wl,
          const float* __restrict__ bias,
          const float* __restrict__ lnw,
          const float* __restrict__ lnb,
          float* __restrict__ out, int N) {
    __shared__ float Ws[KC][D];   // 32 KB
    __shared__ float As[BM][KC];  // 8 KB

    int tid  = threadIdx.x;
    int tx   = tid & 31;
    int ty   = tid >> 5;
    int row0 = blockIdx.x * BM;

    float acc[4][4] = {};

    #pragma unroll
    for (int kc = 0; kc < 4; kc++) {
        int k0 = kc * KC;
        __syncthreads();
        // Load W chunk: rows k0..k0+KC-1 of [W_gcn ; W_lin], 2048 float4s
        for (int i = tid; i < KC * (D / 4); i += 256) {
            int kk = i >> 5;            // 0..63
            int c4 = i & 31;            // float4 index within row
            int kglob = k0 + kk;
            const float* wsrc = (kglob < D) ? (Wg + kglob * D)
                                            : (Wl + (kglob - D) * D);
            ((float4*)&Ws[kk][0])[c4] = ((const float4*)wsrc)[c4];
        }
        // Load A chunk: 32 rows x 64 k. k<128 -> aggx (in `out`), else -> x.
        for (int i = tid; i < BM * (KC / 4); i += 256) {
            int rr  = i >> 4;           // 0..31
            int k4  = i & 15;           // float4 index within chunk
            int row = row0 + rr;
            float4 v = make_float4(0.f, 0.f, 0.f, 0.f);
            if (row < N) {
                const float* asrc = (k0 < D) ? (out + row * D + k0)
                                             : (x + row * D + (k0 - D));
                v = ((const float4*)asrc)[k4];
            }
            ((float4*)&As[rr][0])[k4] = v;
        }
        __syncthreads();

        #pragma unroll
        for (int k = 0; k < KC; k += 4) {
            float4 a[4], w[4];
            #pragma unroll
            for (int rr = 0; rr < 4; rr++)
                a[rr] = *(const float4*)&As[ty * 4 + rr][k];
            #pragma unroll
            for (int kk = 0; kk < 4; kk++)
                w[kk] = *(const float4*)&Ws[k + kk][tx * 4];
            #pragma unroll
            for (int rr = 0; rr < 4; rr++) {
                float4 ar = a[rr];
                acc[rr][0] = fmaf(ar.x, w[0].x, acc[rr][0]);
                acc[rr][1] = fmaf(ar.x, w[0].y, acc[rr][1]);
                acc[rr][2] = fmaf(ar.x, w[0].z, acc[rr][2]);
                acc[rr][3] = fmaf(ar.x, w[0].w, acc[rr][3]);
                acc[rr][0] = fmaf(ar.y, w[1].x, acc[rr][0]);
                acc[rr][1] = fmaf(ar.y, w[1].y, acc[rr][1]);
                acc[rr][2] = fmaf(ar.y, w[1].z, acc[rr][2]);
                acc[rr][3] = fmaf(ar.y, w[1].w, acc[rr][3]);
                acc[rr][0] = fmaf(ar.z, w[2].x, acc[rr][0]);
                acc[rr][1] = fmaf(ar.z, w[2].y, acc[rr][1]);
                acc[rr][2] = fmaf(ar.z, w[2].z, acc[rr][2]);
                acc[rr][3] = fmaf(ar.z, w[2].w, acc[rr][3]);
                acc[rr][0] = fmaf(ar.w, w[3].x, acc[rr][0]);
                acc[rr][1] = fmaf(ar.w, w[3].y, acc[rr][1]);
                acc[rr][2] = fmaf(ar.w, w[3].z, acc[rr][2]);
                acc[rr][3] = fmaf(ar.w, w[3].w, acc[rr][3]);
            }
        }
    }

    // bias + eps
    float4 bv  = ((const float4*)bias)[tx];
    float4 lwv = ((const float4*)lnw)[tx];
    float4 lbv = ((const float4*)lnb)[tx];
    #pragma unroll
    for (int rr = 0; rr < 4; rr++) {
        acc[rr][0] += bv.x + 1e-6f;
        acc[rr][1] += bv.y + 1e-6f;
        acc[rr][2] += bv.z + 1e-6f;
        acc[rr][3] += bv.w + 1e-6f;
    }

    // LayerNorm per row (each warp = one ty = 4 rows across 32 lanes)
    #pragma unroll
    for (int rr = 0; rr < 4; rr++) {
        int row = row0 + ty * 4 + rr;
        float s  = acc[rr][0] + acc[rr][1] + acc[rr][2] + acc[rr][3];
        float s2 = acc[rr][0] * acc[rr][0] + acc[rr][1] * acc[rr][1]
                 + acc[rr][2] * acc[rr][2] + acc[rr][3] * acc[rr][3];
        #pragma unroll
        for (int off = 16; off > 0; off >>= 1) {
            s  += __shfl_xor_sync(0xFFFFFFFFu, s,  off);
            s2 += __shfl_xor_sync(0xFFFFFFFFu, s2, off);
        }
        float mu   = s * (1.0f / D);
        float var  = fmaxf(s2 * (1.0f / D) - mu * mu, 0.0f);
        float rstd = rsqrtf(var + 1e-5f);
        if (row < N) {
            float4 o;
            o.x = (acc[rr][0] - mu) * rstd * lwv.x + lbv.x;
            o.y = (acc[rr][1] - mu) * rstd * lwv.y + lbv.y;
            o.z = (acc[rr][2] - mu) * rstd * lwv.z + lbv.z;
            o.w = (acc[rr][3] - mu) * rstd * lwv.w + lbv.w;
            ((float4*)(out + row * D))[tx] = o;
        }
    }
}

// ---------------------------------------------------------------------------
extern "C" void kernel_launch(void* const* d_in, const int* in_sizes, int n_in,
                              void* d_out, int out_size) {
    const int*   adj = (const int*)d_in[0];
    const float* x   = (const float*)d_in[1];
    const float* Wg  = (const float*)d_in[2];
    const float* bg  = (const float*)d_in[3];
    const float* Wl  = (const float*)d_in[4];
    const float* lnw = (const float*)d_in[5];
    const float* lnb = (const float*)d_in[6];
    float*       out = (float*)d_out;

    int E = in_sizes[0] / 2;
    int N = in_sizes[1] / D;

    k_deg_init<<<(N + 255) / 256, 256>>>(N);
    k_deg_count<<<(E + 255) / 256, 256>>>(adj, E);

    int initThreads = N * (D / 4);
    k_init_agg<<<(initThreads + 255) / 256, 256>>>((const float4*)x, (float4*)out, N);

    long long scatterThreads = (long long)E * 32;
    int scatterBlocks = (int)((scatterThreads + 255) / 256);
    k_scatter<<<scatterBlocks, 256>>>(adj, (const float4*)x, (float4*)out, E);

    int gemmBlocks = (N + BM - 1) / BM;
    k_gemm_ln<<<gemmBlocks, 256>>>(x, Wg, Wl, bg, lnw, lnb, out, N);
}

// round 4
// speedup vs baseline: 1.0398x; 1.0398x over previous
#include <cuda_runtime.h>
#include <cuda_bf16.h>

// Problem constants (fixed by the dataset): N=50000, E=800000, D=128.
#define D 128
#define MAXN 65536
#define MAXE 1048576

__device__ int   g_deg[MAXN];
__device__ float g_dinv[MAXN];
__device__ int   g_rowStart[MAXN + 1];
__device__ int   g_cursor[MAXN];
__device__ int   g_csr_src[MAXE];
__device__ float g_csr_w[MAXE];

// ---------------------------------------------------------------------------
// K1: deg[i] = 1 (self-loop)
// ---------------------------------------------------------------------------
__global__ void k_deg_init(int N) {
    int i = blockIdx.x * blockDim.x + threadIdx.x;
    if (i < N) g_deg[i] = 1;
}

// ---------------------------------------------------------------------------
// K2: deg[dst[e]] += 1
// ---------------------------------------------------------------------------
__global__ void k_deg_count(const int* __restrict__ adj, int E) {
    int e = blockIdx.x * blockDim.x + threadIdx.x;
    if (e < E) atomicAdd(&g_deg[adj[E + e]], 1);
}

// ---------------------------------------------------------------------------
// K3: dinv[i] = rsqrt(deg[i])
// ---------------------------------------------------------------------------
__global__ void k_dinv(int N) {
    int i = blockIdx.x * blockDim.x + threadIdx.x;
    if (i < N) g_dinv[i] = rsqrtf((float)g_deg[i]);
}

// ---------------------------------------------------------------------------
// K4: single-block exclusive scan of (deg[i]-1) -> rowStart, cursor.
// 1024 threads, chunked over N. rowStart[N] = total edge count.
// ---------------------------------------------------------------------------
__global__ void __launch_bounds__(1024) k_scan(int N) {
    __shared__ int wsum[32];
    __shared__ int s_carry;
    int tid = threadIdx.x, lane = tid & 31, wid = tid >> 5;
    if (tid == 0) s_carry = 0;
    __syncthreads();
    for (int base = 0; base < N; base += 1024) {
        int i = base + tid;
        int v = (i < N) ? (g_deg[i] - 1) : 0;
        // inclusive warp scan
        int inc = v;
        #pragma unroll
        for (int o = 1; o < 32; o <<= 1) {
            int t = __shfl_up_sync(0xFFFFFFFFu, inc, o);
            if (lane >= o) inc += t;
        }
        if (lane == 31) wsum[wid] = inc;
        __syncthreads();
        if (wid == 0) {
            int w = wsum[lane];
            int winc = w;
            #pragma unroll
            for (int o = 1; o < 32; o <<= 1) {
                int t = __shfl_up_sync(0xFFFFFFFFu, winc, o);
                if (lane >= o) winc += t;
            }
            wsum[lane] = winc - w;  // exclusive warp offsets
        }
        __syncthreads();
        int excl = s_carry + wsum[wid] + (inc - v);
        if (i < N) { g_rowStart[i] = excl; g_cursor[i] = excl; }
        __syncthreads();
        if (tid == 1023) s_carry += wsum[31] + inc;  // += block total
        __syncthreads();
    }
    if (tid == 0) g_rowStart[N] = s_carry;
}

// ---------------------------------------------------------------------------
// K5: fill CSR: for each edge, pos = cursor[dst]++; store src + weight.
// ---------------------------------------------------------------------------
__global__ void k_fill(const int* __restrict__ adj, int E) {
    int e = blockIdx.x * blockDim.x + threadIdx.x;
    if (e >= E) return;
    int s = __ldg(&adj[e]);
    int t = __ldg(&adj[E + e]);
    float w = g_dinv[s] * g_dinv[t];
    int pos = atomicAdd(&g_cursor[t], 1);
    g_csr_src[pos] = s;
    g_csr_w[pos]   = w;
}

// ---------------------------------------------------------------------------
// K6: aggregation by gather — one warp per node.
//   out[n] = dinv[n]^2 * x[n] + sum_{e in CSR[n]} w_e * x[src_e]
// ---------------------------------------------------------------------------
__global__ void __launch_bounds__(256) k_agg(const float4* __restrict__ x4,
                                             float4* __restrict__ out4, int N) {
    int gt   = blockIdx.x * blockDim.x + threadIdx.x;
    int node = gt >> 5;
    int lane = gt & 31;
    if (node >= N) return;

    float dv = g_dinv[node];
    float4 v = x4[node * 32 + lane];
    float w0 = dv * dv;
    float4 acc0 = make_float4(v.x * w0, v.y * w0, v.z * w0, v.w * w0);
    float4 acc1 = make_float4(0.f, 0.f, 0.f, 0.f);

    int beg = g_rowStart[node];
    int end = g_rowStart[node + 1];

    int i = beg;
    for (; i + 1 < end; i += 2) {
        int   s0 = g_csr_src[i];
        int   s1 = g_csr_src[i + 1];
        float w0e = g_csr_w[i];
        float w1e = g_csr_w[i + 1];
        float4 a = x4[s0 * 32 + lane];
        float4 b = x4[s1 * 32 + lane];
        acc0.x = fmaf(w0e, a.x, acc0.x); acc0.y = fmaf(w0e, a.y, acc0.y);
        acc0.z = fmaf(w0e, a.z, acc0.z); acc0.w = fmaf(w0e, a.w, acc0.w);
        acc1.x = fmaf(w1e, b.x, acc1.x); acc1.y = fmaf(w1e, b.y, acc1.y);
        acc1.z = fmaf(w1e, b.z, acc1.z); acc1.w = fmaf(w1e, b.w, acc1.w);
    }
    if (i < end) {
        int   s0 = g_csr_src[i];
        float we = g_csr_w[i];
        float4 a = x4[s0 * 32 + lane];
        acc0.x = fmaf(we, a.x, acc0.x); acc0.y = fmaf(we, a.y, acc0.y);
        acc0.z = fmaf(we, a.z, acc0.z); acc0.w = fmaf(we, a.w, acc0.w);
    }
    acc0.x += acc1.x; acc0.y += acc1.y; acc0.z += acc1.z; acc0.w += acc1.w;
    out4[node * 32 + lane] = acc0;
}

// ---------------------------------------------------------------------------
// K7: fused GEMM (K=256: [aggx | x] @ [W_gcn ; W_lin]) + bias + eps + LayerNorm
// Block: 256 threads, 32 rows x 128 cols; thread = 4 rows x 4 cols.
// ---------------------------------------------------------------------------
#define BM 32
#define KC 64

__global__ void __launch_bounds__(256)
k_gemm_ln(const float* __restrict__ x,
          const float* __restrict__ Wg,
          const float* __restrict__ Wl,
          const float* __restrict__ bias,
          const float* __restrict__ lnw,
          const float* __restrict__ lnb,
          float* __restrict__ out, int N) {
    __shared__ float Ws[KC][D];   // 32 KB
    __shared__ float As[BM][KC];  // 8 KB

    int tid  = threadIdx.x;
    int tx   = tid & 31;
    int ty   = tid >> 5;
    int row0 = blockIdx.x * BM;

    float acc[4][4] = {};

    #pragma unroll
    for (int kc = 0; kc < 4; kc++) {
        int k0 = kc * KC;
        __syncthreads();
        for (int i = tid; i < KC * (D / 4); i += 256) {
            int kk = i >> 5;
            int c4 = i & 31;
            int kglob = k0 + kk;
            const float* wsrc = (kglob < D) ? (Wg + kglob * D)
                                            : (Wl + (kglob - D) * D);
            ((float4*)&Ws[kk][0])[c4] = ((const float4*)wsrc)[c4];
        }
        for (int i = tid; i < BM * (KC / 4); i += 256) {
            int rr  = i >> 4;
            int k4  = i & 15;
            int row = row0 + rr;
            float4 v = make_float4(0.f, 0.f, 0.f, 0.f);
            if (row < N) {
                const float* asrc = (k0 < D) ? (out + row * D + k0)
                                             : (x + row * D + (k0 - D));
                v = ((const float4*)asrc)[k4];
            }
            ((float4*)&As[rr][0])[k4] = v;
        }
        __syncthreads();

        #pragma unroll
        for (int k = 0; k < KC; k += 4) {
            float4 a[4], w[4];
            #pragma unroll
            for (int rr = 0; rr < 4; rr++)
                a[rr] = *(const float4*)&As[ty * 4 + rr][k];
            #pragma unroll
            for (int kk = 0; kk < 4; kk++)
                w[kk] = *(const float4*)&Ws[k + kk][tx * 4];
            #pragma unroll
            for (int rr = 0; rr < 4; rr++) {
                float4 ar = a[rr];
                acc[rr][0] = fmaf(ar.x, w[0].x, acc[rr][0]);
                acc[rr][1] = fmaf(ar.x, w[0].y, acc[rr][1]);
                acc[rr][2] = fmaf(ar.x, w[0].z, acc[rr][2]);
                acc[rr][3] = fmaf(ar.x, w[0].w, acc[rr][3]);
                acc[rr][0] = fmaf(ar.y, w[1].x, acc[rr][0]);
                acc[rr][1] = fmaf(ar.y, w[1].y, acc[rr][1]);
                acc[rr][2] = fmaf(ar.y, w[1].z, acc[rr][2]);
                acc[rr][3] = fmaf(ar.y, w[1].w, acc[rr][3]);
                acc[rr][0] = fmaf(ar.z, w[2].x, acc[rr][0]);
                acc[rr][1] = fmaf(ar.z, w[2].y, acc[rr][1]);
                acc[rr][2] = fmaf(ar.z, w[2].z, acc[rr][2]);
                acc[rr][3] = fmaf(ar.z, w[2].w, acc[rr][3]);
                acc[rr][0] = fmaf(ar.w, w[3].x, acc[rr][0]);
                acc[rr][1] = fmaf(ar.w, w[3].y, acc[rr][1]);
                acc[rr][2] = fmaf(ar.w, w[3].z, acc[rr][2]);
                acc[rr][3] = fmaf(ar.w, w[3].w, acc[rr][3]);
            }
        }
    }

    float4 bv  = ((const float4*)bias)[tx];
    float4 lwv = ((const float4*)lnw)[tx];
    float4 lbv = ((const float4*)lnb)[tx];
    #pragma unroll
    for (int rr = 0; rr < 4; rr++) {
        acc[rr][0] += bv.x + 1e-6f;
        acc[rr][1] += bv.y + 1e-6f;
        acc[rr][2] += bv.z + 1e-6f;
        acc[rr][3] += bv.w + 1e-6f;
    }

    #pragma unroll
    for (int rr = 0; rr < 4; rr++) {
        int row = row0 + ty * 4 + rr;
        float s  = acc[rr][0] + acc[rr][1] + acc[rr][2] + acc[rr][3];
        float s2 = acc[rr][0] * acc[rr][0] + acc[rr][1] * acc[rr][1]
                 + acc[rr][2] * acc[rr][2] + acc[rr][3] * acc[rr][3];
        #pragma unroll
        for (int off = 16; off > 0; off >>= 1) {
            s  += __shfl_xor_sync(0xFFFFFFFFu, s,  off);
            s2 += __shfl_xor_sync(0xFFFFFFFFu, s2, off);
        }
        float mu   = s * (1.0f / D);
        float var  = fmaxf(s2 * (1.0f / D) - mu * mu, 0.0f);
        float rstd = rsqrtf(var + 1e-5f);
        if (row < N) {
            float4 o;
            o.x = (acc[rr][0] - mu) * rstd * lwv.x + lbv.x;
            o.y = (acc[rr][1] - mu) * rstd * lwv.y + lbv.y;
            o.z = (acc[rr][2] - mu) * rstd * lwv.z + lbv.z;
            o.w = (acc[rr][3] - mu) * rstd * lwv.w + lbv.w;
            ((float4*)(out + row * D))[tx] = o;
        }
    }
}

// ---------------------------------------------------------------------------
extern "C" void kernel_launch(void* const* d_in, const int* in_sizes, int n_in,
                              void* d_out, int out_size) {
    const int*   adj = (const int*)d_in[0];
    const float* x   = (const float*)d_in[1];
    const float* Wg  = (const float*)d_in[2];
    const float* bg  = (const float*)d_in[3];
    const float* Wl  = (const float*)d_in[4];
    const float* lnw = (const float*)d_in[5];
    const float* lnb = (const float*)d_in[6];
    float*       out = (float*)d_out;

    int E = in_sizes[0] / 2;
    int N = in_sizes[1] / D;

    k_deg_init<<<(N + 255) / 256, 256>>>(N);
    k_deg_count<<<(E + 255) / 256, 256>>>(adj, E);
    k_dinv<<<(N + 255) / 256, 256>>>(N);
    k_scan<<<1, 1024>>>(N);
    k_fill<<<(E + 255) / 256, 256>>>(adj, E);

    int aggThreads = N * 32;
    k_agg<<<(aggThreads + 255) / 256, 256>>>((const float4*)x, (float4*)out, N);

    int gemmBlocks = (N + BM - 1) / BM;
    k_gemm_ln<<<gemmBlocks, 256>>>(x, Wg, Wl, bg, lnw, lnb, out, N);
}

// round 7
// speedup vs baseline: 1.2434x; 1.1958x over previous
#include <cuda_runtime.h>
#include <cuda_bf16.h>

// Problem constants (fixed by the dataset): N=50000, E=800000, D=128.
#define D 128
#define MAXN 65536
#define MAXE 1048576
#define SCAN_B 1024
#define MAXBLK 64

__device__ int   g_deg[MAXN];
__device__ float g_dinv[MAXN];
__device__ int   g_rowStart[MAXN + 1];
__device__ int   g_cursor[MAXN];
__device__ int   g_csr_src[MAXE];
__device__ float g_csr_w[MAXE];
__device__ int   g_blockSums[MAXBLK];

// ---------------------------------------------------------------------------
// K1: deg[i] = 1 (self-loop)
// ---------------------------------------------------------------------------
__global__ void k_deg_init(int N) {
    int i = blockIdx.x * blockDim.x + threadIdx.x;
    if (i < N) g_deg[i] = 1;
}

// ---------------------------------------------------------------------------
// K2: deg[dst[e]] += 1
// ---------------------------------------------------------------------------
__global__ void k_deg_count(const int* __restrict__ adj, int E) {
    int e = blockIdx.x * blockDim.x + threadIdx.x;
    if (e < E) atomicAdd(&g_deg[adj[E + e]], 1);
}

// ---------------------------------------------------------------------------
// K3a: per-block exclusive scan of (deg-1); local result -> rowStart,
//      block total -> g_blockSums. Also computes dinv (fused).
// ---------------------------------------------------------------------------
__global__ void __launch_bounds__(SCAN_B) k_scan_partial(int N) {
    __shared__ int wsum[32];
    int tid = threadIdx.x, lane = tid & 31, wid = tid >> 5;
    int i = blockIdx.x * SCAN_B + tid;
    int deg = (i < N) ? g_deg[i] : 1;
    if (i < N) g_dinv[i] = rsqrtf((float)deg);
    int v = deg - 1;
    // inclusive warp scan
    int inc = v;
    #pragma unroll
    for (int o = 1; o < 32; o <<= 1) {
        int t = __shfl_up_sync(0xFFFFFFFFu, inc, o);
        if (lane >= o) inc += t;
    }
    if (lane == 31) wsum[wid] = inc;
    __syncthreads();
    if (wid == 0) {
        int w = wsum[lane];
        int winc = w;
        #pragma unroll
        for (int o = 1; o < 32; o <<= 1) {
            int t = __shfl_up_sync(0xFFFFFFFFu, winc, o);
            if (lane >= o) winc += t;
        }
        wsum[lane] = winc - w;  // exclusive warp offsets
        if (lane == 31) g_blockSums[blockIdx.x] = winc;  // block total
    }
    __syncthreads();
    if (i < N) g_rowStart[i] = wsum[wid] + (inc - v);
}

// ---------------------------------------------------------------------------
// K3b: exclusive scan of block sums (nb <= 64, one warp, serial-ish is fine)
// ---------------------------------------------------------------------------
__global__ void k_scan_mid(int nb) {
    if (threadIdx.x == 0) {
        int run = 0;
        for (int b = 0; b < nb; b++) {
            int t = g_blockSums[b];
            g_blockSums[b] = run;
            run += t;
        }
    }
}

// ---------------------------------------------------------------------------
// K3c: add block offsets; write rowStart + cursor; rowStart[N] = E.
// ---------------------------------------------------------------------------
__global__ void __launch_bounds__(SCAN_B) k_scan_add(int N, int E) {
    int i = blockIdx.x * SCAN_B + threadIdx.x;
    if (i < N) {
        int val = g_rowStart[i] + g_blockSums[blockIdx.x];
        g_rowStart[i] = val;
        g_cursor[i]   = val;
    }
    if (i == 0) g_rowStart[N] = E;
}

// ---------------------------------------------------------------------------
// K5: fill CSR: for each edge, pos = cursor[dst]++; store src + weight.
// ---------------------------------------------------------------------------
__global__ void k_fill(const int* __restrict__ adj, int E) {
    int e = blockIdx.x * blockDim.x + threadIdx.x;
    if (e >= E) return;
    int s = __ldg(&adj[e]);
    int t = __ldg(&adj[E + e]);
    float w = g_dinv[s] * g_dinv[t];
    int pos = atomicAdd(&g_cursor[t], 1);
    g_csr_src[pos] = s;
    g_csr_w[pos]   = w;
}

// ---------------------------------------------------------------------------
// K6: aggregation by gather — one warp per node.
//   out[n] = dinv[n]^2 * x[n] + sum_{e in CSR[n]} w_e * x[src_e]
// ---------------------------------------------------------------------------
__global__ void __launch_bounds__(256) k_agg(const float4* __restrict__ x4,
                                             float4* __restrict__ out4, int N) {
    int gt   = blockIdx.x * blockDim.x + threadIdx.x;
    int node = gt >> 5;
    int lane = gt & 31;
    if (node >= N) return;

    float dv = g_dinv[node];
    float4 v = x4[node * 32 + lane];
    float w0 = dv * dv;
    float4 acc0 = make_float4(v.x * w0, v.y * w0, v.z * w0, v.w * w0);
    float4 acc1 = make_float4(0.f, 0.f, 0.f, 0.f);

    int beg = g_rowStart[node];
    int end = g_rowStart[node + 1];

    int i = beg;
    for (; i + 1 < end; i += 2) {
        int   s0 = g_csr_src[i];
        int   s1 = g_csr_src[i + 1];
        float w0e = g_csr_w[i];
        float w1e = g_csr_w[i + 1];
        float4 a = x4[s0 * 32 + lane];
        float4 b = x4[s1 * 32 + lane];
        acc0.x = fmaf(w0e, a.x, acc0.x); acc0.y = fmaf(w0e, a.y, acc0.y);
        acc0.z = fmaf(w0e, a.z, acc0.z); acc0.w = fmaf(w0e, a.w, acc0.w);
        acc1.x = fmaf(w1e, b.x, acc1.x); acc1.y = fmaf(w1e, b.y, acc1.y);
        acc1.z = fmaf(w1e, b.z, acc1.z); acc1.w = fmaf(w1e, b.w, acc1.w);
    }
    if (i < end) {
        int   s0 = g_csr_src[i];
        float we = g_csr_w[i];
        float4 a = x4[s0 * 32 + lane];
        acc0.x = fmaf(we, a.x, acc0.x); acc0.y = fmaf(we, a.y, acc0.y);
        acc0.z = fmaf(we, a.z, acc0.z); acc0.w = fmaf(we, a.w, acc0.w);
    }
    acc0.x += acc1.x; acc0.y += acc1.y; acc0.z += acc1.z; acc0.w += acc1.w;
    out4[node * 32 + lane] = acc0;
}

// ---------------------------------------------------------------------------
// K7: fused GEMM (K=256: [aggx | x] @ [W_gcn ; W_lin]) + bias + eps + LayerNorm
// Block: 256 threads, 32 rows x 128 cols; thread = 4 rows x 4 cols.
// ---------------------------------------------------------------------------
#define BM 32
#define KC 64

__global__ void __launch_bounds__(256)
k_gemm_ln(const float* __restrict__ x,
          const float* __restrict__ Wg,
          const float* __restrict__ Wl,
          const float* __restrict__ bias,
          const float* __restrict__ lnw,
          const float* __restrict__ lnb,
          float* __restrict__ out, int N) {
    __shared__ float Ws[KC][D];   // 32 KB
    __shared__ float As[BM][KC];  // 8 KB

    int tid  = threadIdx.x;
    int tx   = tid & 31;
    int ty   = tid >> 5;
    int row0 = blockIdx.x * BM;

    float acc[4][4] = {};

    #pragma unroll
    for (int kc = 0; kc < 4; kc++) {
        int k0 = kc * KC;
        __syncthreads();
        for (int i = tid; i < KC * (D / 4); i += 256) {
            int kk = i >> 5;
            int c4 = i & 31;
            int kglob = k0 + kk;
            const float* wsrc = (kglob < D) ? (Wg + kglob * D)
                                            : (Wl + (kglob - D) * D);
            ((float4*)&Ws[kk][0])[c4] = ((const float4*)wsrc)[c4];
        }
        for (int i = tid; i < BM * (KC / 4); i += 256) {
            int rr  = i >> 4;
            int k4  = i & 15;
            int row = row0 + rr;
            float4 v = make_float4(0.f, 0.f, 0.f, 0.f);
            if (row < N) {
                const float* asrc = (k0 < D) ? (out + row * D + k0)
                                             : (x + row * D + (k0 - D));
                v = ((const float4*)asrc)[k4];
            }
            ((float4*)&As[rr][0])[k4] = v;
        }
        __syncthreads();

        #pragma unroll
        for (int k = 0; k < KC; k += 4) {
            float4 a[4], w[4];
            #pragma unroll
            for (int rr = 0; rr < 4; rr++)
                a[rr] = *(const float4*)&As[ty * 4 + rr][k];
            #pragma unroll
            for (int kk = 0; kk < 4; kk++)
                w[kk] = *(const float4*)&Ws[k + kk][tx * 4];
            #pragma unroll
            for (int rr = 0; rr < 4; rr++) {
                float4 ar = a[rr];
                acc[rr][0] = fmaf(ar.x, w[0].x, acc[rr][0]);
                acc[rr][1] = fmaf(ar.x, w[0].y, acc[rr][1]);
                acc[rr][2] = fmaf(ar.x, w[0].z, acc[rr][2]);
                acc[rr][3] = fmaf(ar.x, w[0].w, acc[rr][3]);
                acc[rr][0] = fmaf(ar.y, w[1].x, acc[rr][0]);
                acc[rr][1] = fmaf(ar.y, w[1].y, acc[rr][1]);
                acc[rr][2] = fmaf(ar.y, w[1].z, acc[rr][2]);
                acc[rr][3] = fmaf(ar.y, w[1].w, acc[rr][3]);
                acc[rr][0] = fmaf(ar.z, w[2].x, acc[rr][0]);
                acc[rr][1] = fmaf(ar.z, w[2].y, acc[rr][1]);
                acc[rr][2] = fmaf(ar.z, w[2].z, acc[rr][2]);
                acc[rr][3] = fmaf(ar.z, w[2].w, acc[rr][3]);
                acc[rr][0] = fmaf(ar.w, w[3].x, acc[rr][0]);
                acc[rr][1] = fmaf(ar.w, w[3].y, acc[rr][1]);
                acc[rr][2] = fmaf(ar.w, w[3].z, acc[rr][2]);
                acc[rr][3] = fmaf(ar.w, w[3].w, acc[rr][3]);
            }
        }
    }

    float4 bv  = ((const float4*)bias)[tx];
    float4 lwv = ((const float4*)lnw)[tx];
    float4 lbv = ((const float4*)lnb)[tx];
    #pragma unroll
    for (int rr = 0; rr < 4; rr++) {
        acc[rr][0] += bv.x + 1e-6f;
        acc[rr][1] += bv.y + 1e-6f;
        acc[rr][2] += bv.z + 1e-6f;
        acc[rr][3] += bv.w + 1e-6f;
    }

    #pragma unroll
    for (int rr = 0; rr < 4; rr++) {
        int row = row0 + ty * 4 + rr;
        float s  = acc[rr][0] + acc[rr][1] + acc[rr][2] + acc[rr][3];
        float s2 = acc[rr][0] * acc[rr][0] + acc[rr][1] * acc[rr][1]
                 + acc[rr][2] * acc[rr][2] + acc[rr][3] * acc[rr][3];
        #pragma unroll
        for (int off = 16; off > 0; off >>= 1) {
            s  += __shfl_xor_sync(0xFFFFFFFFu, s,  off);
            s2 += __shfl_xor_sync(0xFFFFFFFFu, s2, off);
        }
        float mu   = s * (1.0f / D);
        float var  = fmaxf(s2 * (1.0f / D) - mu * mu, 0.0f);
        float rstd = rsqrtf(var + 1e-5f);
        if (row < N) {
            float4 o;
            o.x = (acc[rr][0] - mu) * rstd * lwv.x + lbv.x;
            o.y = (acc[rr][1] - mu) * rstd * lwv.y + lbv.y;
            o.z = (acc[rr][2] - mu) * rstd * lwv.z + lbv.z;
            o.w = (acc[rr][3] - mu) * rstd * lwv.w + lbv.w;
            ((float4*)(out + row * D))[tx] = o;
        }
    }
}

// ---------------------------------------------------------------------------
extern "C" void kernel_launch(void* const* d_in, const int* in_sizes, int n_in,
                              void* d_out, int out_size) {
    const int*   adj = (const int*)d_in[0];
    const float* x   = (const float*)d_in[1];
    const float* Wg  = (const float*)d_in[2];
    const float* bg  = (const float*)d_in[3];
    const float* Wl  = (const float*)d_in[4];
    const float* lnw = (const float*)d_in[5];
    const float* lnb = (const float*)d_in[6];
    float*       out = (float*)d_out;

    int E = in_sizes[0] / 2;
    int N = in_sizes[1] / D;
    int nb = (N + SCAN_B - 1) / SCAN_B;

    k_deg_init<<<(N + 255) / 256, 256>>>(N);
    k_deg_count<<<(E + 255) / 256, 256>>>(adj, E);
    k_scan_partial<<<nb, SCAN_B>>>(N);
    k_scan_mid<<<1, 32>>>(nb);
    k_scan_add<<<nb, SCAN_B>>>(N, E);
    k_fill<<<(E + 255) / 256, 256>>>(adj, E);

    int aggThreads = N * 32;
    k_agg<<<(aggThreads + 255) / 256, 256>>>((const float4*)x, (float4*)out, N);

    int gemmBlocks = (N + BM - 1) / BM;
    k_gemm_ln<<<gemmBlocks, 256>>>(x, Wg, Wl, bg, lnw, lnb, out, N);
}